// round 5
// baseline (speedup 1.0000x reference)
#include <cuda_runtime.h>

// ---------------------------------------------------------------------------
// DFMNET: 2-layer LSTM (B=2048, T=256, I=64, H=128) + 6-layer MLP head.
// Persistent CTA per 16 batch rows runs all 256 timesteps.
// R5: 512 threads, 1 gate column x 16 rows per thread (g = tid). Weights
// pre-duplicated f32x2, layout [k/2][512][2] -> one LDG.128 per 2-k chunk per
// thread, zero weight-load redundancy across threads. Activation reads are
// warp-broadcast LDS.128. FMA pipe is the designed binder (~128 cyc / 2-k
// per SMSP vs ~108 issue cyc).
// ---------------------------------------------------------------------------

#define T_SEQ    256
#define I_IN     64
#define H_HID    128
#define ROWS     16            // batch rows per CTA
#define NTHREADS 512
#define KROWS    320           // xh rows: [x(64) | h1(128) | h2(128)]
#define GSTR     516           // gates row stride (pad 4 -> bounded smem conflicts)

typedef unsigned long long ull;

// Repacked weights, duplicated into both f32x2 lanes.
// Layout: [K/2][512 gates][2 k-slots], +1 padded chunk so prefetch never branches.
__device__ __align__(16) ull g_Wt1[(96 + 1) * 1024];    // K=192
__device__ __align__(16) ull g_Wt2[(128 + 1) * 1024];   // K=256
__device__ ull g_b1[512];
__device__ ull g_b2[512];

// ---- packed fp32x2 helpers ----
__device__ __forceinline__ ull fma2(ull a, ull b, ull c) {
    ull d;
    asm("fma.rn.f32x2 %0, %1, %2, %3;" : "=l"(d) : "l"(a), "l"(b), "l"(c));
    return d;
}
__device__ __forceinline__ void unpack2(ull v, float& lo, float& hi) {
    unsigned a, b;
    asm("mov.b64 {%0, %1}, %2;" : "=r"(a), "=r"(b) : "l"(v));
    lo = __uint_as_float(a); hi = __uint_as_float(b);
}
__device__ __forceinline__ ull dup2(float w) {
    ull r; unsigned u = __float_as_uint(w);
    asm("mov.b64 %0, {%1, %1};" : "=l"(r) : "r"(u));
    return r;
}

__device__ __forceinline__ float sigf(float v) {
    return __fdividef(1.f, 1.f + __expf(-v));
}
__device__ __forceinline__ float tanhf_fast(float v) {
    float z = fminf(fmaxf(v, -15.f), 15.f);
    float e = __expf(-2.f * z);
    return __fdividef(1.f - e, 1.f + e);
}

// ---------------------------------------------------------------------------
// Weight repack: fuse (W_ih | W_hh), transpose, duplicate, [k/2][512][2] layout.
// ---------------------------------------------------------------------------
__global__ void prep_kernel(const float* __restrict__ Wih1, const float* __restrict__ Whh1,
                            const float* __restrict__ bih1, const float* __restrict__ bhh1,
                            const float* __restrict__ Wih2, const float* __restrict__ Whh2,
                            const float* __restrict__ bih2, const float* __restrict__ bhh2)
{
    int tid = blockIdx.x * blockDim.x + threadIdx.x;
    int stride = gridDim.x * blockDim.x;
    if (tid < 512) {
        g_b1[tid] = dup2(bih1[tid] + bhh1[tid]);
        g_b2[tid] = dup2(bih2[tid] + bhh2[tid]);
    }
    // layer 1: 97 chunks (chunk 96 = zero pad)
    for (int e = tid; e < 97 * 1024; e += stride) {
        int c = e >> 10, g = (e >> 1) & 511, s = e & 1;
        int k = 2 * c + s;
        float w = 0.f;
        if (k < 192) w = (k < 64) ? Wih1[g * 64 + k] : Whh1[g * 128 + (k - 64)];
        g_Wt1[e] = dup2(w);
    }
    // layer 2: 129 chunks (chunk 128 = zero pad)
    for (int e = tid; e < 129 * 1024; e += stride) {
        int c = e >> 10, g = (e >> 1) & 511, s = e & 1;
        int k = 2 * c + s;
        float w = 0.f;
        if (k < 256) w = (k < 128) ? Wih2[g * 128 + k] : Whh2[g * 128 + (k - 128)];
        g_Wt2[e] = dup2(w);
    }
}

// ---------------------------------------------------------------------------
// Gate GEMM: gates[16][GSTR] = bias + xh[16][K] @ Wt[K][512]
// Thread owns gate column g = tid, all 16 rows in 8 f32x2 accumulators.
// Weights: 1 LDG.128 per 2-k chunk, double-buffered (padded tail, no branch).
// Activations: 8 broadcast LDS.128 per chunk (2 k-rows, contiguous in smem).
// ---------------------------------------------------------------------------
__device__ __forceinline__ void gemm_gates(const ull* __restrict__ Wt,
                                           const ull* __restrict__ bias,
                                           const float* __restrict__ xh,   // [k][16]
                                           float* __restrict__ gates,      // [16][GSTR]
                                           int K, int g)
{
    ull acc[8];
    {
        ull b = bias[g];
#pragma unroll
        for (int p = 0; p < 8; p++) acc[p] = b;
    }

    const ulonglong2* wp = (const ulonglong2*)Wt + g;   // chunk stride = 512 ulonglong2
    const int nch = K >> 1;
    ulonglong2 wc = wp[0];

#pragma unroll 4
    for (int c = 0; c < nch; c++) {
        ulonglong2 wn = wp[512];            // padded: safe to read one past
        wp += 512;
        const ulonglong2* xr = (const ulonglong2*)(xh + (c << 5));  // 2 k-rows = 32 floats
        ulonglong2 q0 = xr[0], q1 = xr[1], q2 = xr[2], q3 = xr[3];  // k = 2c
        ulonglong2 q4 = xr[4], q5 = xr[5], q6 = xr[6], q7 = xr[7];  // k = 2c+1
        acc[0] = fma2(wc.x, q0.x, acc[0]);
        acc[1] = fma2(wc.x, q0.y, acc[1]);
        acc[2] = fma2(wc.x, q1.x, acc[2]);
        acc[3] = fma2(wc.x, q1.y, acc[3]);
        acc[4] = fma2(wc.x, q2.x, acc[4]);
        acc[5] = fma2(wc.x, q2.y, acc[5]);
        acc[6] = fma2(wc.x, q3.x, acc[6]);
        acc[7] = fma2(wc.x, q3.y, acc[7]);
        acc[0] = fma2(wc.y, q4.x, acc[0]);
        acc[1] = fma2(wc.y, q4.y, acc[1]);
        acc[2] = fma2(wc.y, q5.x, acc[2]);
        acc[3] = fma2(wc.y, q5.y, acc[3]);
        acc[4] = fma2(wc.y, q6.x, acc[4]);
        acc[5] = fma2(wc.y, q6.y, acc[5]);
        acc[6] = fma2(wc.y, q7.x, acc[6]);
        acc[7] = fma2(wc.y, q7.y, acc[7]);
        wc = wn;
    }

    // acc[p] = rows (2p, 2p+1); lanes write consecutive g -> coalesced STS
    float* gp = gates + g;
#pragma unroll
    for (int p = 0; p < 8; p++) {
        float lo, hi;
        unpack2(acc[p], lo, hi);
        gp[(2 * p)     * GSTR] = lo;
        gp[(2 * p + 1) * GSTR] = hi;
    }
}

// Small MLP layer over the CTA's 16 rows (head only; negligible cost)
__device__ __forceinline__ void mlp_layer(const float* __restrict__ vin, int Din,
                                          const float* __restrict__ W, const float* __restrict__ b,
                                          float* __restrict__ vout, int Dout, bool relu, int tid)
{
    for (int e = tid; e < ROWS * Dout; e += NTHREADS) {
        int r = e / Dout, o = e - r * Dout;
        const float* w = W + o * Din;
        const float* vi = vin + r * Din;
        float s = b[o];
        for (int i = 0; i < Din; i += 4) {
            s += w[i] * vi[i] + w[i + 1] * vi[i + 1] + w[i + 2] * vi[i + 2] + w[i + 3] * vi[i + 3];
        }
        vout[e] = relu ? fmaxf(s, 0.f) : s;
    }
    __syncthreads();
}

// ---------------------------------------------------------------------------
__global__ void __launch_bounds__(NTHREADS, 1)
dfmnet_main(const float* __restrict__ x,
            const float* __restrict__ Wk0, const float* __restrict__ bk0,
            const float* __restrict__ Wk1, const float* __restrict__ bk1,
            const float* __restrict__ Wk2, const float* __restrict__ bk2,
            const float* __restrict__ Wk3, const float* __restrict__ bk3,
            const float* __restrict__ Wk4, const float* __restrict__ bk4,
            const float* __restrict__ Wk5, const float* __restrict__ bk5,
            float* __restrict__ out, int Bn)
{
    extern __shared__ float sm[];
    float* xh    = sm;                      // [KROWS][16]  (k-major, 16 rows)
    float* gates = sm + KROWS * ROWS;       // [16][GSTR]

    const int tid = threadIdx.x;
    const int b0 = blockIdx.x * ROWS;

    for (int e = tid; e < KROWS * ROWS; e += NTHREADS) xh[e] = 0.f;
    float c1r[4], c2r[4];
#pragma unroll
    for (int p = 0; p < 4; p++) { c1r[p] = 0.f; c2r[p] = 0.f; }
    __syncthreads();

    const float* xbase = x + (size_t)b0 * T_SEQ * I_IN;

    for (int t = 0; t < T_SEQ; t++) {
        // load x_t (16 rows x 64) transposed into xh rows [0,64)
#pragma unroll
        for (int q = 0; q < 2; q++) {
            int e = tid + q * NTHREADS;            // 0..1023
            int r = e >> 6, k = e & 63;
            xh[k * ROWS + r] = xbase[(size_t)r * (T_SEQ * I_IN) + t * I_IN + k];
        }
        __syncthreads();

        // layer 1: gates = [x | h1_prev] @ Wt1 + b1
        gemm_gates(g_Wt1, g_b1, xh, gates, 192, tid);
        __syncthreads();

        // layer 1 activation: h1 -> xh rows [64,192)
#pragma unroll
        for (int p = 0; p < 4; p++) {
            int idx = tid + p * NTHREADS;          // 0..2047
            int j = idx >> 4, r = idx & 15;
            const float* gr = gates + r * GSTR + j;
            float iv = sigf(gr[0]);
            float fv = sigf(gr[128]);
            float gv = tanhf_fast(gr[256]);
            float ov = sigf(gr[384]);
            float c = fv * c1r[p] + iv * gv;
            c1r[p] = c;
            xh[(64 + j) * ROWS + r] = ov * tanhf_fast(c);
        }
        __syncthreads();

        // layer 2: gates = [h1 | h2_prev] @ Wt2 + b2  (xh rows [64,320))
        gemm_gates(g_Wt2, g_b2, xh + 64 * ROWS, gates, 256, tid);
        __syncthreads();

        // layer 2 activation: h2 -> xh rows [192,320)
#pragma unroll
        for (int p = 0; p < 4; p++) {
            int idx = tid + p * NTHREADS;
            int j = idx >> 4, r = idx & 15;
            const float* gr = gates + r * GSTR + j;
            float iv = sigf(gr[0]);
            float fv = sigf(gr[128]);
            float gv = tanhf_fast(gr[256]);
            float ov = sigf(gr[384]);
            float c = fv * c2r[p] + iv * gv;
            c2r[p] = c;
            xh[(192 + j) * ROWS + r] = ov * tanhf_fast(c);
        }
        // next iter's x-load writes disjoint smem; its __syncthreads orders
        // these h2 writes (and this phase's gates reads) before reuse.
    }
    __syncthreads();

    // ---- outputs: tuple (y, h2, r) flattened ----
    float* out_y  = out;                              // [Bn][64]
    float* out_h2 = out + (size_t)Bn * 64;            // [Bn][128]
    float* out_r  = out + (size_t)Bn * 192;           // [Bn][192]

    float* va = gates;              // [16][192]
    float* vb = gates + ROWS * 192; // [16][128]
    float* vc = vb + ROWS * 128;    // [16][128]
    for (int e = tid; e < ROWS * 192; e += NTHREADS) {
        int r = e / 192, j = e - r * 192;
        float v = (j < 128) ? xh[(192 + j) * ROWS + r] : xh[(j - 128) * ROWS + r];
        va[e] = v;
        out_r[(size_t)(b0 + r) * 192 + j] = v;
        if (j < 128) out_h2[(size_t)(b0 + r) * 128 + j] = v;
    }
    __syncthreads();

    mlp_layer(va, 192, Wk0, bk0, vb, 128, true, tid);
    mlp_layer(vb, 128, Wk1, bk1, vc, 128, true, tid);
    mlp_layer(vc, 128, Wk2, bk2, vb, 128, true, tid);
    mlp_layer(vb, 128, Wk3, bk3, vc, 128, true, tid);
    mlp_layer(vc, 128, Wk4, bk4, vb, 128, true, tid);

    for (int e = tid; e < ROWS * 64; e += NTHREADS) {
        int r = e >> 6, o = e & 63;
        const float* w = Wk5 + o * 128;
        const float* vi = vb + r * 128;
        float s = bk5[o];
        for (int i = 0; i < 128; i += 4) {
            s += w[i] * vi[i] + w[i + 1] * vi[i + 1] + w[i + 2] * vi[i + 2] + w[i + 3] * vi[i + 3];
        }
        out_y[(size_t)(b0 + r) * 64 + o] = s;
    }
}

// ---------------------------------------------------------------------------
extern "C" void kernel_launch(void* const* d_in, const int* in_sizes, int n_in,
                              void* d_out, int out_size)
{
    const float* x    = (const float*)d_in[0];
    const float* Wih1 = (const float*)d_in[1];
    const float* Whh1 = (const float*)d_in[2];
    const float* bih1 = (const float*)d_in[3];
    const float* bhh1 = (const float*)d_in[4];
    const float* Wih2 = (const float*)d_in[5];
    const float* Whh2 = (const float*)d_in[6];
    const float* bih2 = (const float*)d_in[7];
    const float* bhh2 = (const float*)d_in[8];
    const float* Wk0 = (const float*)d_in[9];   const float* bk0 = (const float*)d_in[10];
    const float* Wk1 = (const float*)d_in[11];  const float* bk1 = (const float*)d_in[12];
    const float* Wk2 = (const float*)d_in[13];  const float* bk2 = (const float*)d_in[14];
    const float* Wk3 = (const float*)d_in[15];  const float* bk3 = (const float*)d_in[16];
    const float* Wk4 = (const float*)d_in[17];  const float* bk4 = (const float*)d_in[18];
    const float* Wk5 = (const float*)d_in[19];  const float* bk5 = (const float*)d_in[20];

    int Bn = in_sizes[0] / (T_SEQ * I_IN);
    int smem_bytes = (KROWS * ROWS + ROWS * GSTR) * (int)sizeof(float);   // 53504 B

    cudaFuncSetAttribute(dfmnet_main, cudaFuncAttributeMaxDynamicSharedMemorySize, smem_bytes);

    prep_kernel<<<208, 256>>>(Wih1, Whh1, bih1, bhh1, Wih2, Whh2, bih2, bhh2);
    dfmnet_main<<<Bn / ROWS, NTHREADS, smem_bytes>>>(
        x, Wk0, bk0, Wk1, bk1, Wk2, bk2, Wk3, bk3, Wk4, bk4, Wk5, bk5,
        (float*)d_out, Bn);
}

// round 6
// speedup vs baseline: 1.5012x; 1.5012x over previous
#include <cuda_runtime.h>

// ---------------------------------------------------------------------------
// DFMNET: 2-layer LSTM (B=2048, T=256, I=64, H=128) + 6-layer MLP head.
// Persistent CTA per 16 batch rows runs all 256 timesteps.
// R6: split-K. 512 threads = 2 k-groups x 256 cols-threads. Each thread owns
// 2 gate columns x 16 rows (16 FFMA2 per k, 4 broadcast LDS.128 per k) over
// HALF the K range -> R3's FMA:LDS ratio (the proven best) with 4 warps/SMSP
// for latency hiding. Groups write partial-gate buffers; activation sums them.
// Weights plain fp32 k-major [k/2][512][2] -> one LDG.64 per col per 2-k,
// branchless double-buffered prefetch (padded tail).
// ---------------------------------------------------------------------------

#define T_SEQ    256
#define I_IN     64
#define H_HID    128
#define ROWS     16            // batch rows per CTA
#define NTHREADS 512
#define KROWS    320           // xh rows: [x(64) | h1(128) | h2(128)]
#define GSTR     516           // gates row stride (pad 4 -> 2-way act reads)

typedef unsigned long long ull;

// Weights: [chunk][512 cols] float2 = (w[2c,col], w[2c+1,col]); +1 pad chunk
// so the prefetch can always read one chunk ahead without a branch.
__device__ __align__(16) float2 g_Wt1[(96 + 1) * 512];    // K=192 -> 96 chunks
__device__ __align__(16) float2 g_Wt2[(128 + 1) * 512];   // K=256 -> 128 chunks
__device__ float g_b1[512];
__device__ float g_b2[512];

// ---- packed fp32x2 helpers ----
__device__ __forceinline__ ull fma2(ull a, ull b, ull c) {
    ull d;
    asm("fma.rn.f32x2 %0, %1, %2, %3;" : "=l"(d) : "l"(a), "l"(b), "l"(c));
    return d;
}
__device__ __forceinline__ void unpack2(ull v, float& lo, float& hi) {
    unsigned a, b;
    asm("mov.b64 {%0, %1}, %2;" : "=r"(a), "=r"(b) : "l"(v));
    lo = __uint_as_float(a); hi = __uint_as_float(b);
}
__device__ __forceinline__ ull dup2(float w) {
    ull r; unsigned u = __float_as_uint(w);
    asm("mov.b64 %0, {%1, %1};" : "=l"(r) : "r"(u));
    return r;
}

__device__ __forceinline__ float sigf(float v) {
    return __fdividef(1.f, 1.f + __expf(-v));
}
__device__ __forceinline__ float tanhf_fast(float v) {
    float z = fminf(fmaxf(v, -15.f), 15.f);
    float e = __expf(-2.f * z);
    return __fdividef(1.f - e, 1.f + e);
}

// ---------------------------------------------------------------------------
// Weight repack: fuse (W_ih | W_hh), transpose to k-major, pair k's into float2.
// ---------------------------------------------------------------------------
__global__ void prep_kernel(const float* __restrict__ Wih1, const float* __restrict__ Whh1,
                            const float* __restrict__ bih1, const float* __restrict__ bhh1,
                            const float* __restrict__ Wih2, const float* __restrict__ Whh2,
                            const float* __restrict__ bih2, const float* __restrict__ bhh2)
{
    int tid = blockIdx.x * blockDim.x + threadIdx.x;
    int stride = gridDim.x * blockDim.x;
    if (tid < 512) {
        g_b1[tid] = bih1[tid] + bhh1[tid];
        g_b2[tid] = bih2[tid] + bhh2[tid];
    }
    for (int e = tid; e < 97 * 512; e += stride) {
        int c = e >> 9, g = e & 511;
        int k0 = 2 * c, k1 = 2 * c + 1;
        float w0 = 0.f, w1 = 0.f;
        if (k0 < 192) w0 = (k0 < 64) ? Wih1[g * 64 + k0] : Whh1[g * 128 + (k0 - 64)];
        if (k1 < 192) w1 = (k1 < 64) ? Wih1[g * 64 + k1] : Whh1[g * 128 + (k1 - 64)];
        g_Wt1[e] = make_float2(w0, w1);
    }
    for (int e = tid; e < 129 * 512; e += stride) {
        int c = e >> 9, g = e & 511;
        int k0 = 2 * c, k1 = 2 * c + 1;
        float w0 = 0.f, w1 = 0.f;
        if (k0 < 256) w0 = (k0 < 128) ? Wih2[g * 128 + k0] : Whh2[g * 128 + (k0 - 128)];
        if (k1 < 256) w1 = (k1 < 128) ? Wih2[g * 128 + k1] : Whh2[g * 128 + (k1 - 128)];
        g_Wt2[e] = make_float2(w0, w1);
    }
}

// ---------------------------------------------------------------------------
// Partial gate GEMM over chunk range [cb, cb+nc):
//   gates[16][GSTR] (+= bias if add_bias) = xh[16][2*cb : 2*(cb+nc)] @ Wt-slice
// Thread owns cols (col, col+256), all 16 rows in 16 f32x2 accumulators.
// Per 2-k chunk: 2 LDG.64 (coalesced, double-buffered), 8 broadcast LDS.128,
// 32 FFMA2, 4 dup MOVs. FMA pipe is the binder (~78% issue occupancy).
// ---------------------------------------------------------------------------
__device__ __forceinline__ void gemm_gates(const float2* __restrict__ Wt,
                                           const float* __restrict__ bias,
                                           const float* __restrict__ xh,   // [k][16]
                                           float* __restrict__ gates,      // [16][GSTR]
                                           int cb, int nc, int col, bool add_bias)
{
    ull acc0[8], acc1[8];
    if (add_bias) {
        ull b0 = dup2(bias[col]), b1 = dup2(bias[col + 256]);
#pragma unroll
        for (int p = 0; p < 8; p++) { acc0[p] = b0; acc1[p] = b1; }
    } else {
#pragma unroll
        for (int p = 0; p < 8; p++) { acc0[p] = 0ull; acc1[p] = 0ull; }
    }

    const float2* W0 = Wt + cb * 512 + col;
    const float2* W1 = W0 + 256;
    float2 wc0 = *W0, wc1 = *W1;
    const ulonglong2* xr = (const ulonglong2*)(xh + cb * 32);

#pragma unroll 2
    for (int c = 0; c < nc; c++) {
        W0 += 512; W1 += 512;
        float2 wn0 = *W0, wn1 = *W1;          // prefetch next chunk (padded tail)
        // activations: k = 2(cb+c) rows 0..15 (q0..q3), k+1 (q4..q7)
        ulonglong2 q0 = xr[0], q1 = xr[1], q2 = xr[2], q3 = xr[3];
        ulonglong2 q4 = xr[4], q5 = xr[5], q6 = xr[6], q7 = xr[7];
        xr += 8;

        ull wa0 = dup2(wc0.x), wa1 = dup2(wc1.x);
        acc0[0] = fma2(wa0, q0.x, acc0[0]);
        acc0[1] = fma2(wa0, q0.y, acc0[1]);
        acc0[2] = fma2(wa0, q1.x, acc0[2]);
        acc0[3] = fma2(wa0, q1.y, acc0[3]);
        acc0[4] = fma2(wa0, q2.x, acc0[4]);
        acc0[5] = fma2(wa0, q2.y, acc0[5]);
        acc0[6] = fma2(wa0, q3.x, acc0[6]);
        acc0[7] = fma2(wa0, q3.y, acc0[7]);
        acc1[0] = fma2(wa1, q0.x, acc1[0]);
        acc1[1] = fma2(wa1, q0.y, acc1[1]);
        acc1[2] = fma2(wa1, q1.x, acc1[2]);
        acc1[3] = fma2(wa1, q1.y, acc1[3]);
        acc1[4] = fma2(wa1, q2.x, acc1[4]);
        acc1[5] = fma2(wa1, q2.y, acc1[5]);
        acc1[6] = fma2(wa1, q3.x, acc1[6]);
        acc1[7] = fma2(wa1, q3.y, acc1[7]);

        ull wb0 = dup2(wc0.y), wb1 = dup2(wc1.y);
        acc0[0] = fma2(wb0, q4.x, acc0[0]);
        acc0[1] = fma2(wb0, q4.y, acc0[1]);
        acc0[2] = fma2(wb0, q5.x, acc0[2]);
        acc0[3] = fma2(wb0, q5.y, acc0[3]);
        acc0[4] = fma2(wb0, q6.x, acc0[4]);
        acc0[5] = fma2(wb0, q6.y, acc0[5]);
        acc0[6] = fma2(wb0, q7.x, acc0[6]);
        acc0[7] = fma2(wb0, q7.y, acc0[7]);
        acc1[0] = fma2(wb1, q4.x, acc1[0]);
        acc1[1] = fma2(wb1, q4.y, acc1[1]);
        acc1[2] = fma2(wb1, q5.x, acc1[2]);
        acc1[3] = fma2(wb1, q5.y, acc1[3]);
        acc1[4] = fma2(wb1, q6.x, acc1[4]);
        acc1[5] = fma2(wb1, q6.y, acc1[5]);
        acc1[6] = fma2(wb1, q7.x, acc1[6]);
        acc1[7] = fma2(wb1, q7.y, acc1[7]);

        wc0 = wn0; wc1 = wn1;
    }

    // acc[p] = rows (2p, 2p+1); lanes write consecutive cols -> conflict-free
    float* gp0 = gates + col;
    float* gp1 = gates + col + 256;
#pragma unroll
    for (int p = 0; p < 8; p++) {
        float lo, hi;
        unpack2(acc0[p], lo, hi);
        gp0[(2 * p)     * GSTR] = lo;
        gp0[(2 * p + 1) * GSTR] = hi;
        unpack2(acc1[p], lo, hi);
        gp1[(2 * p)     * GSTR] = lo;
        gp1[(2 * p + 1) * GSTR] = hi;
    }
}

// Small MLP layer over the CTA's 16 rows (head only; negligible cost)
__device__ __forceinline__ void mlp_layer(const float* __restrict__ vin, int Din,
                                          const float* __restrict__ W, const float* __restrict__ b,
                                          float* __restrict__ vout, int Dout, bool relu, int tid)
{
    for (int e = tid; e < ROWS * Dout; e += NTHREADS) {
        int r = e / Dout, o = e - r * Dout;
        const float* w = W + o * Din;
        const float* vi = vin + r * Din;
        float s = b[o];
        for (int i = 0; i < Din; i += 4) {
            s += w[i] * vi[i] + w[i + 1] * vi[i + 1] + w[i + 2] * vi[i + 2] + w[i + 3] * vi[i + 3];
        }
        vout[e] = relu ? fmaxf(s, 0.f) : s;
    }
    __syncthreads();
}

// ---------------------------------------------------------------------------
__global__ void __launch_bounds__(NTHREADS, 1)
dfmnet_main(const float* __restrict__ x,
            const float* __restrict__ Wk0, const float* __restrict__ bk0,
            const float* __restrict__ Wk1, const float* __restrict__ bk1,
            const float* __restrict__ Wk2, const float* __restrict__ bk2,
            const float* __restrict__ Wk3, const float* __restrict__ bk3,
            const float* __restrict__ Wk4, const float* __restrict__ bk4,
            const float* __restrict__ Wk5, const float* __restrict__ bk5,
            float* __restrict__ out, int Bn)
{
    extern __shared__ float sm[];
    float* xh     = sm;                          // [KROWS][16]
    float* gates0 = sm + KROWS * ROWS;           // [16][GSTR] partial, group 0 (+bias)
    float* gates1 = gates0 + ROWS * GSTR;        // [16][GSTR] partial, group 1

    const int tid = threadIdx.x;
    const int grp = tid >> 8;                    // k-group 0/1 (warps 0-7 / 8-15)
    const int col = tid & 255;
    const int b0 = blockIdx.x * ROWS;

    for (int e = tid; e < KROWS * ROWS; e += NTHREADS) xh[e] = 0.f;
    float c1r[4], c2r[4];
#pragma unroll
    for (int p = 0; p < 4; p++) { c1r[p] = 0.f; c2r[p] = 0.f; }
    __syncthreads();

    const float* xbase = x + (size_t)b0 * T_SEQ * I_IN;
    float* mygates = grp ? gates1 : gates0;

    for (int t = 0; t < T_SEQ; t++) {
        // load x_t (16 rows x 64) transposed into xh rows [0,64)
#pragma unroll
        for (int q = 0; q < 2; q++) {
            int e = tid + q * NTHREADS;            // 0..1023
            int r = e >> 6, k = e & 63;
            xh[k * ROWS + r] = xbase[(size_t)r * (T_SEQ * I_IN) + t * I_IN + k];
        }
        __syncthreads();

        // layer 1: K=192 split 96/96 (48 chunks per group)
        gemm_gates(g_Wt1, g_b1, xh, mygates, grp * 48, 48, col, grp == 0);
        __syncthreads();

        // layer 1 activation: h1 -> xh rows [64,192); sum the two partials
#pragma unroll
        for (int p = 0; p < 4; p++) {
            int idx = tid + p * NTHREADS;          // 0..2047
            int j = idx >> 4, r = idx & 15;
            const float* ga = gates0 + r * GSTR + j;
            const float* gb = gates1 + r * GSTR + j;
            float iv = sigf(ga[0]   + gb[0]);
            float fv = sigf(ga[128] + gb[128]);
            float gv = tanhf_fast(ga[256] + gb[256]);
            float ov = sigf(ga[384] + gb[384]);
            float c = fv * c1r[p] + iv * gv;
            c1r[p] = c;
            xh[(64 + j) * ROWS + r] = ov * tanhf_fast(c);
        }
        __syncthreads();

        // layer 2: K=256 split 128/128 (64 chunks per group); xh rows [64,320)
        gemm_gates(g_Wt2, g_b2, xh + 64 * ROWS, mygates, grp * 64, 64, col, grp == 0);
        __syncthreads();

        // layer 2 activation: h2 -> xh rows [192,320)
#pragma unroll
        for (int p = 0; p < 4; p++) {
            int idx = tid + p * NTHREADS;
            int j = idx >> 4, r = idx & 15;
            const float* ga = gates0 + r * GSTR + j;
            const float* gb = gates1 + r * GSTR + j;
            float iv = sigf(ga[0]   + gb[0]);
            float fv = sigf(ga[128] + gb[128]);
            float gv = tanhf_fast(ga[256] + gb[256]);
            float ov = sigf(ga[384] + gb[384]);
            float c = fv * c2r[p] + iv * gv;
            c2r[p] = c;
            xh[(192 + j) * ROWS + r] = ov * tanhf_fast(c);
        }
        // next iter's x-load writes disjoint smem; its __syncthreads orders
        // these h2 writes (and this phase's gates reads) before reuse.
    }
    __syncthreads();

    // ---- outputs: tuple (y, h2, r) flattened ----
    float* out_y  = out;                              // [Bn][64]
    float* out_h2 = out + (size_t)Bn * 64;            // [Bn][128]
    float* out_r  = out + (size_t)Bn * 192;           // [Bn][192]

    float* va = gates0;              // [16][192]
    float* vb = gates0 + ROWS * 192; // [16][128]
    float* vc = vb + ROWS * 128;     // [16][128]
    for (int e = tid; e < ROWS * 192; e += NTHREADS) {
        int r = e / 192, j = e - r * 192;
        float v = (j < 128) ? xh[(192 + j) * ROWS + r] : xh[(j - 128) * ROWS + r];
        va[e] = v;
        out_r[(size_t)(b0 + r) * 192 + j] = v;
        if (j < 128) out_h2[(size_t)(b0 + r) * 128 + j] = v;
    }
    __syncthreads();

    mlp_layer(va, 192, Wk0, bk0, vb, 128, true, tid);
    mlp_layer(vb, 128, Wk1, bk1, vc, 128, true, tid);
    mlp_layer(vc, 128, Wk2, bk2, vb, 128, true, tid);
    mlp_layer(vb, 128, Wk3, bk3, vc, 128, true, tid);
    mlp_layer(vc, 128, Wk4, bk4, vb, 128, true, tid);

    for (int e = tid; e < ROWS * 64; e += NTHREADS) {
        int r = e >> 6, o = e & 63;
        const float* w = Wk5 + o * 128;
        const float* vi = vb + r * 128;
        float s = bk5[o];
        for (int i = 0; i < 128; i += 4) {
            s += w[i] * vi[i] + w[i + 1] * vi[i + 1] + w[i + 2] * vi[i + 2] + w[i + 3] * vi[i + 3];
        }
        out_y[(size_t)(b0 + r) * 64 + o] = s;
    }
}

// ---------------------------------------------------------------------------
extern "C" void kernel_launch(void* const* d_in, const int* in_sizes, int n_in,
                              void* d_out, int out_size)
{
    const float* x    = (const float*)d_in[0];
    const float* Wih1 = (const float*)d_in[1];
    const float* Whh1 = (const float*)d_in[2];
    const float* bih1 = (const float*)d_in[3];
    const float* bhh1 = (const float*)d_in[4];
    const float* Wih2 = (const float*)d_in[5];
    const float* Whh2 = (const float*)d_in[6];
    const float* bih2 = (const float*)d_in[7];
    const float* bhh2 = (const float*)d_in[8];
    const float* Wk0 = (const float*)d_in[9];   const float* bk0 = (const float*)d_in[10];
    const float* Wk1 = (const float*)d_in[11];  const float* bk1 = (const float*)d_in[12];
    const float* Wk2 = (const float*)d_in[13];  const float* bk2 = (const float*)d_in[14];
    const float* Wk3 = (const float*)d_in[15];  const float* bk3 = (const float*)d_in[16];
    const float* Wk4 = (const float*)d_in[17];  const float* bk4 = (const float*)d_in[18];
    const float* Wk5 = (const float*)d_in[19];  const float* bk5 = (const float*)d_in[20];

    int Bn = in_sizes[0] / (T_SEQ * I_IN);
    int smem_bytes = (KROWS * ROWS + 2 * ROWS * GSTR) * (int)sizeof(float);  // 86528 B

    cudaFuncSetAttribute(dfmnet_main, cudaFuncAttributeMaxDynamicSharedMemorySize, smem_bytes);

    prep_kernel<<<208, 256>>>(Wih1, Whh1, bih1, bhh1, Wih2, Whh2, bih2, bhh2);
    dfmnet_main<<<Bn / ROWS, NTHREADS, smem_bytes>>>(
        x, Wk0, bk0, Wk1, bk1, Wk2, bk2, Wk3, bk3, Wk4, bk4, Wk5, bk5,
        (float*)d_out, Bn);
}

// round 7
// speedup vs baseline: 1.5036x; 1.0016x over previous
#include <cuda_runtime.h>

// ---------------------------------------------------------------------------
// DFMNET: 2-layer LSTM (B=2048, T=256, I=64, H=128) + 6-layer MLP head.
// Persistent CTA per 16 batch rows runs all 256 timesteps.
// R6: split-K. 512 threads = 2 k-groups x 256 cols-threads. Each thread owns
// 2 gate columns x 16 rows (16 FFMA2 per k, 4 broadcast LDS.128 per k) over
// HALF the K range -> R3's FMA:LDS ratio (the proven best) with 4 warps/SMSP
// for latency hiding. Groups write partial-gate buffers; activation sums them.
// Weights plain fp32 k-major [k/2][512][2] -> one LDG.64 per col per 2-k,
// branchless double-buffered prefetch (padded tail).
// ---------------------------------------------------------------------------

#define T_SEQ    256
#define I_IN     64
#define H_HID    128
#define ROWS     16            // batch rows per CTA
#define NTHREADS 512
#define KROWS    320           // xh rows: [x(64) | h1(128) | h2(128)]
#define GSTR     516           // gates row stride (pad 4 -> 2-way act reads)

typedef unsigned long long ull;

// Weights: [chunk][512 cols] float2 = (w[2c,col], w[2c+1,col]); +1 pad chunk
// so the prefetch can always read one chunk ahead without a branch.
__device__ __align__(16) float2 g_Wt1[(96 + 1) * 512];    // K=192 -> 96 chunks
__device__ __align__(16) float2 g_Wt2[(128 + 1) * 512];   // K=256 -> 128 chunks
__device__ float g_b1[512];
__device__ float g_b2[512];

// ---- packed fp32x2 helpers ----
__device__ __forceinline__ ull fma2(ull a, ull b, ull c) {
    ull d;
    asm("fma.rn.f32x2 %0, %1, %2, %3;" : "=l"(d) : "l"(a), "l"(b), "l"(c));
    return d;
}
__device__ __forceinline__ void unpack2(ull v, float& lo, float& hi) {
    unsigned a, b;
    asm("mov.b64 {%0, %1}, %2;" : "=r"(a), "=r"(b) : "l"(v));
    lo = __uint_as_float(a); hi = __uint_as_float(b);
}
__device__ __forceinline__ ull dup2(float w) {
    ull r; unsigned u = __float_as_uint(w);
    asm("mov.b64 %0, {%1, %1};" : "=l"(r) : "r"(u));
    return r;
}

__device__ __forceinline__ float sigf(float v) {
    return __fdividef(1.f, 1.f + __expf(-v));
}
__device__ __forceinline__ float tanhf_fast(float v) {
    float z = fminf(fmaxf(v, -15.f), 15.f);
    float e = __expf(-2.f * z);
    return __fdividef(1.f - e, 1.f + e);
}

// ---------------------------------------------------------------------------
// Weight repack: fuse (W_ih | W_hh), transpose to k-major, pair k's into float2.
// ---------------------------------------------------------------------------
__global__ void prep_kernel(const float* __restrict__ Wih1, const float* __restrict__ Whh1,
                            const float* __restrict__ bih1, const float* __restrict__ bhh1,
                            const float* __restrict__ Wih2, const float* __restrict__ Whh2,
                            const float* __restrict__ bih2, const float* __restrict__ bhh2)
{
    int tid = blockIdx.x * blockDim.x + threadIdx.x;
    int stride = gridDim.x * blockDim.x;
    if (tid < 512) {
        g_b1[tid] = bih1[tid] + bhh1[tid];
        g_b2[tid] = bih2[tid] + bhh2[tid];
    }
    for (int e = tid; e < 97 * 512; e += stride) {
        int c = e >> 9, g = e & 511;
        int k0 = 2 * c, k1 = 2 * c + 1;
        float w0 = 0.f, w1 = 0.f;
        if (k0 < 192) w0 = (k0 < 64) ? Wih1[g * 64 + k0] : Whh1[g * 128 + (k0 - 64)];
        if (k1 < 192) w1 = (k1 < 64) ? Wih1[g * 64 + k1] : Whh1[g * 128 + (k1 - 64)];
        g_Wt1[e] = make_float2(w0, w1);
    }
    for (int e = tid; e < 129 * 512; e += stride) {
        int c = e >> 9, g = e & 511;
        int k0 = 2 * c, k1 = 2 * c + 1;
        float w0 = 0.f, w1 = 0.f;
        if (k0 < 256) w0 = (k0 < 128) ? Wih2[g * 128 + k0] : Whh2[g * 128 + (k0 - 128)];
        if (k1 < 256) w1 = (k1 < 128) ? Wih2[g * 128 + k1] : Whh2[g * 128 + (k1 - 128)];
        g_Wt2[e] = make_float2(w0, w1);
    }
}

// ---------------------------------------------------------------------------
// Partial gate GEMM over chunk range [cb, cb+nc):
//   gates[16][GSTR] (+= bias if add_bias) = xh[16][2*cb : 2*(cb+nc)] @ Wt-slice
// Thread owns cols (col, col+256), all 16 rows in 16 f32x2 accumulators.
// Per 2-k chunk: 2 LDG.64 (coalesced, double-buffered), 8 broadcast LDS.128,
// 32 FFMA2, 4 dup MOVs. FMA pipe is the binder (~78% issue occupancy).
// ---------------------------------------------------------------------------
__device__ __forceinline__ void gemm_gates(const float2* __restrict__ Wt,
                                           const float* __restrict__ bias,
                                           const float* __restrict__ xh,   // [k][16]
                                           float* __restrict__ gates,      // [16][GSTR]
                                           int cb, int nc, int col, bool add_bias)
{
    ull acc0[8], acc1[8];
    if (add_bias) {
        ull b0 = dup2(bias[col]), b1 = dup2(bias[col + 256]);
#pragma unroll
        for (int p = 0; p < 8; p++) { acc0[p] = b0; acc1[p] = b1; }
    } else {
#pragma unroll
        for (int p = 0; p < 8; p++) { acc0[p] = 0ull; acc1[p] = 0ull; }
    }

    const float2* W0 = Wt + cb * 512 + col;
    const float2* W1 = W0 + 256;
    float2 wc0 = *W0, wc1 = *W1;
    const ulonglong2* xr = (const ulonglong2*)(xh + cb * 32);

#pragma unroll 2
    for (int c = 0; c < nc; c++) {
        W0 += 512; W1 += 512;
        float2 wn0 = *W0, wn1 = *W1;          // prefetch next chunk (padded tail)
        // activations: k = 2(cb+c) rows 0..15 (q0..q3), k+1 (q4..q7)
        ulonglong2 q0 = xr[0], q1 = xr[1], q2 = xr[2], q3 = xr[3];
        ulonglong2 q4 = xr[4], q5 = xr[5], q6 = xr[6], q7 = xr[7];
        xr += 8;

        ull wa0 = dup2(wc0.x), wa1 = dup2(wc1.x);
        acc0[0] = fma2(wa0, q0.x, acc0[0]);
        acc0[1] = fma2(wa0, q0.y, acc0[1]);
        acc0[2] = fma2(wa0, q1.x, acc0[2]);
        acc0[3] = fma2(wa0, q1.y, acc0[3]);
        acc0[4] = fma2(wa0, q2.x, acc0[4]);
        acc0[5] = fma2(wa0, q2.y, acc0[5]);
        acc0[6] = fma2(wa0, q3.x, acc0[6]);
        acc0[7] = fma2(wa0, q3.y, acc0[7]);
        acc1[0] = fma2(wa1, q0.x, acc1[0]);
        acc1[1] = fma2(wa1, q0.y, acc1[1]);
        acc1[2] = fma2(wa1, q1.x, acc1[2]);
        acc1[3] = fma2(wa1, q1.y, acc1[3]);
        acc1[4] = fma2(wa1, q2.x, acc1[4]);
        acc1[5] = fma2(wa1, q2.y, acc1[5]);
        acc1[6] = fma2(wa1, q3.x, acc1[6]);
        acc1[7] = fma2(wa1, q3.y, acc1[7]);

        ull wb0 = dup2(wc0.y), wb1 = dup2(wc1.y);
        acc0[0] = fma2(wb0, q4.x, acc0[0]);
        acc0[1] = fma2(wb0, q4.y, acc0[1]);
        acc0[2] = fma2(wb0, q5.x, acc0[2]);
        acc0[3] = fma2(wb0, q5.y, acc0[3]);
        acc0[4] = fma2(wb0, q6.x, acc0[4]);
        acc0[5] = fma2(wb0, q6.y, acc0[5]);
        acc0[6] = fma2(wb0, q7.x, acc0[6]);
        acc0[7] = fma2(wb0, q7.y, acc0[7]);
        acc1[0] = fma2(wb1, q4.x, acc1[0]);
        acc1[1] = fma2(wb1, q4.y, acc1[1]);
        acc1[2] = fma2(wb1, q5.x, acc1[2]);
        acc1[3] = fma2(wb1, q5.y, acc1[3]);
        acc1[4] = fma2(wb1, q6.x, acc1[4]);
        acc1[5] = fma2(wb1, q6.y, acc1[5]);
        acc1[6] = fma2(wb1, q7.x, acc1[6]);
        acc1[7] = fma2(wb1, q7.y, acc1[7]);

        wc0 = wn0; wc1 = wn1;
    }

    // acc[p] = rows (2p, 2p+1); lanes write consecutive cols -> conflict-free
    float* gp0 = gates + col;
    float* gp1 = gates + col + 256;
#pragma unroll
    for (int p = 0; p < 8; p++) {
        float lo, hi;
        unpack2(acc0[p], lo, hi);
        gp0[(2 * p)     * GSTR] = lo;
        gp0[(2 * p + 1) * GSTR] = hi;
        unpack2(acc1[p], lo, hi);
        gp1[(2 * p)     * GSTR] = lo;
        gp1[(2 * p + 1) * GSTR] = hi;
    }
}

// Small MLP layer over the CTA's 16 rows (head only; negligible cost)
__device__ __forceinline__ void mlp_layer(const float* __restrict__ vin, int Din,
                                          const float* __restrict__ W, const float* __restrict__ b,
                                          float* __restrict__ vout, int Dout, bool relu, int tid)
{
    for (int e = tid; e < ROWS * Dout; e += NTHREADS) {
        int r = e / Dout, o = e - r * Dout;
        const float* w = W + o * Din;
        const float* vi = vin + r * Din;
        float s = b[o];
        for (int i = 0; i < Din; i += 4) {
            s += w[i] * vi[i] + w[i + 1] * vi[i + 1] + w[i + 2] * vi[i + 2] + w[i + 3] * vi[i + 3];
        }
        vout[e] = relu ? fmaxf(s, 0.f) : s;
    }
    __syncthreads();
}

// ---------------------------------------------------------------------------
__global__ void __launch_bounds__(NTHREADS, 1)
dfmnet_main(const float* __restrict__ x,
            const float* __restrict__ Wk0, const float* __restrict__ bk0,
            const float* __restrict__ Wk1, const float* __restrict__ bk1,
            const float* __restrict__ Wk2, const float* __restrict__ bk2,
            const float* __restrict__ Wk3, const float* __restrict__ bk3,
            const float* __restrict__ Wk4, const float* __restrict__ bk4,
            const float* __restrict__ Wk5, const float* __restrict__ bk5,
            float* __restrict__ out, int Bn)
{
    extern __shared__ float sm[];
    float* xh     = sm;                          // [KROWS][16]
    float* gates0 = sm + KROWS * ROWS;           // [16][GSTR] partial, group 0 (+bias)
    float* gates1 = gates0 + ROWS * GSTR;        // [16][GSTR] partial, group 1

    const int tid = threadIdx.x;
    const int grp = tid >> 8;                    // k-group 0/1 (warps 0-7 / 8-15)
    const int col = tid & 255;
    const int b0 = blockIdx.x * ROWS;

    for (int e = tid; e < KROWS * ROWS; e += NTHREADS) xh[e] = 0.f;
    float c1r[4], c2r[4];
#pragma unroll
    for (int p = 0; p < 4; p++) { c1r[p] = 0.f; c2r[p] = 0.f; }
    __syncthreads();

    const float* xbase = x + (size_t)b0 * T_SEQ * I_IN;
    float* mygates = grp ? gates1 : gates0;

    for (int t = 0; t < T_SEQ; t++) {
        // load x_t (16 rows x 64) transposed into xh rows [0,64)
#pragma unroll
        for (int q = 0; q < 2; q++) {
            int e = tid + q * NTHREADS;            // 0..1023
            int r = e >> 6, k = e & 63;
            xh[k * ROWS + r] = xbase[(size_t)r * (T_SEQ * I_IN) + t * I_IN + k];
        }
        __syncthreads();

        // layer 1: K=192 split 96/96 (48 chunks per group)
        gemm_gates(g_Wt1, g_b1, xh, mygates, grp * 48, 48, col, grp == 0);
        __syncthreads();

        // layer 1 activation: h1 -> xh rows [64,192); sum the two partials
#pragma unroll
        for (int p = 0; p < 4; p++) {
            int idx = tid + p * NTHREADS;          // 0..2047
            int j = idx >> 4, r = idx & 15;
            const float* ga = gates0 + r * GSTR + j;
            const float* gb = gates1 + r * GSTR + j;
            float iv = sigf(ga[0]   + gb[0]);
            float fv = sigf(ga[128] + gb[128]);
            float gv = tanhf_fast(ga[256] + gb[256]);
            float ov = sigf(ga[384] + gb[384]);
            float c = fv * c1r[p] + iv * gv;
            c1r[p] = c;
            xh[(64 + j) * ROWS + r] = ov * tanhf_fast(c);
        }
        __syncthreads();

        // layer 2: K=256 split 128/128 (64 chunks per group); xh rows [64,320)
        gemm_gates(g_Wt2, g_b2, xh + 64 * ROWS, mygates, grp * 64, 64, col, grp == 0);
        __syncthreads();

        // layer 2 activation: h2 -> xh rows [192,320)
#pragma unroll
        for (int p = 0; p < 4; p++) {
            int idx = tid + p * NTHREADS;
            int j = idx >> 4, r = idx & 15;
            const float* ga = gates0 + r * GSTR + j;
            const float* gb = gates1 + r * GSTR + j;
            float iv = sigf(ga[0]   + gb[0]);
            float fv = sigf(ga[128] + gb[128]);
            float gv = tanhf_fast(ga[256] + gb[256]);
            float ov = sigf(ga[384] + gb[384]);
            float c = fv * c2r[p] + iv * gv;
            c2r[p] = c;
            xh[(192 + j) * ROWS + r] = ov * tanhf_fast(c);
        }
        // next iter's x-load writes disjoint smem; its __syncthreads orders
        // these h2 writes (and this phase's gates reads) before reuse.
    }
    __syncthreads();

    // ---- outputs: tuple (y, h2, r) flattened ----
    float* out_y  = out;                              // [Bn][64]
    float* out_h2 = out + (size_t)Bn * 64;            // [Bn][128]
    float* out_r  = out + (size_t)Bn * 192;           // [Bn][192]

    float* va = gates0;              // [16][192]
    float* vb = gates0 + ROWS * 192; // [16][128]
    float* vc = vb + ROWS * 128;     // [16][128]
    for (int e = tid; e < ROWS * 192; e += NTHREADS) {
        int r = e / 192, j = e - r * 192;
        float v = (j < 128) ? xh[(192 + j) * ROWS + r] : xh[(j - 128) * ROWS + r];
        va[e] = v;
        out_r[(size_t)(b0 + r) * 192 + j] = v;
        if (j < 128) out_h2[(size_t)(b0 + r) * 128 + j] = v;
    }
    __syncthreads();

    mlp_layer(va, 192, Wk0, bk0, vb, 128, true, tid);
    mlp_layer(vb, 128, Wk1, bk1, vc, 128, true, tid);
    mlp_layer(vc, 128, Wk2, bk2, vb, 128, true, tid);
    mlp_layer(vb, 128, Wk3, bk3, vc, 128, true, tid);
    mlp_layer(vc, 128, Wk4, bk4, vb, 128, true, tid);

    for (int e = tid; e < ROWS * 64; e += NTHREADS) {
        int r = e >> 6, o = e & 63;
        const float* w = Wk5 + o * 128;
        const float* vi = vb + r * 128;
        float s = bk5[o];
        for (int i = 0; i < 128; i += 4) {
            s += w[i] * vi[i] + w[i + 1] * vi[i + 1] + w[i + 2] * vi[i + 2] + w[i + 3] * vi[i + 3];
        }
        out_y[(size_t)(b0 + r) * 64 + o] = s;
    }
}

// ---------------------------------------------------------------------------
extern "C" void kernel_launch(void* const* d_in, const int* in_sizes, int n_in,
                              void* d_out, int out_size)
{
    const float* x    = (const float*)d_in[0];
    const float* Wih1 = (const float*)d_in[1];
    const float* Whh1 = (const float*)d_in[2];
    const float* bih1 = (const float*)d_in[3];
    const float* bhh1 = (const float*)d_in[4];
    const float* Wih2 = (const float*)d_in[5];
    const float* Whh2 = (const float*)d_in[6];
    const float* bih2 = (const float*)d_in[7];
    const float* bhh2 = (const float*)d_in[8];
    const float* Wk0 = (const float*)d_in[9];   const float* bk0 = (const float*)d_in[10];
    const float* Wk1 = (const float*)d_in[11];  const float* bk1 = (const float*)d_in[12];
    const float* Wk2 = (const float*)d_in[13];  const float* bk2 = (const float*)d_in[14];
    const float* Wk3 = (const float*)d_in[15];  const float* bk3 = (const float*)d_in[16];
    const float* Wk4 = (const float*)d_in[17];  const float* bk4 = (const float*)d_in[18];
    const float* Wk5 = (const float*)d_in[19];  const float* bk5 = (const float*)d_in[20];

    int Bn = in_sizes[0] / (T_SEQ * I_IN);
    int smem_bytes = (KROWS * ROWS + 2 * ROWS * GSTR) * (int)sizeof(float);  // 86528 B

    cudaFuncSetAttribute(dfmnet_main, cudaFuncAttributeMaxDynamicSharedMemorySize, smem_bytes);

    prep_kernel<<<208, 256>>>(Wih1, Whh1, bih1, bhh1, Wih2, Whh2, bih2, bhh2);
    dfmnet_main<<<Bn / ROWS, NTHREADS, smem_bytes>>>(
        x, Wk0, bk0, Wk1, bk1, Wk2, bk2, Wk3, bk3, Wk4, bk4, Wk5, bk5,
        (float*)d_out, Bn);
}